// round 6
// baseline (speedup 1.0000x reference)
#include <cuda_runtime.h>
#include <cuda_bf16.h>
#include <math.h>
#include <stdint.h>

// ---------------------------------------------------------------------------
// Problem constants
// ---------------------------------------------------------------------------
#define BATCH   2
#define CH      192
#define DIM     32
#define SPAT    (DIM*DIM*DIM)      // 32768
#define HID     768
#define KS      7
#define KV      343
#define NCELLS  1024               // 2 * 8*8*8
#define CELLTOK 64                 // 4*4*4

// ---------------------------------------------------------------------------
// Device scratch (static globals -- no runtime allocation)
// ---------------------------------------------------------------------------
__device__ int   g_cellList[NCELLS];
__device__ int   g_cellCount;
__device__ float g_yc[(size_t)NCELLS * CELLTOK * CH];    // compacted conv out
__device__ float g_h [(size_t)NCELLS * CELLTOK * HID];   // hidden activations
__device__ float g_w1r[CH * HID];                        // tf32-rounded w1
__device__ float g_w2r[HID * CH];                        // tf32-rounded w2

// ---------------------------------------------------------------------------
// Helpers
// ---------------------------------------------------------------------------
__device__ __forceinline__ float2 ffma2(float2 a, float2 b, float2 c) {
    union U { float2 f; unsigned long long u; };
    U A, B, C, D;
    A.f = a; B.f = b; C.f = c;
    asm("fma.rn.f32x2 %0, %1, %2, %3;" : "=l"(D.u) : "l"(A.u), "l"(B.u), "l"(C.u));
    return D.f;
}

__device__ __forceinline__ float tf32r(float x) {
    unsigned int u;
    asm("cvt.rna.tf32.f32 %0, %1;" : "=r"(u) : "f"(x));
    return __uint_as_float(u);
}

// mma.sync m16n8k8 tf32: d += a * b   (mapping verified by passing rounds)
__device__ __forceinline__ void mma_tf32(float* d, const float* a, float b0, float b1) {
    asm volatile(
        "mma.sync.aligned.m16n8k8.row.col.f32.tf32.tf32.f32 "
        "{%0,%1,%2,%3}, {%4,%5,%6,%7}, {%8,%9}, {%0,%1,%2,%3};"
        : "+f"(d[0]), "+f"(d[1]), "+f"(d[2]), "+f"(d[3])
        : "r"(__float_as_uint(a[0])), "r"(__float_as_uint(a[1])),
          "r"(__float_as_uint(a[2])), "r"(__float_as_uint(a[3])),
          "r"(__float_as_uint(b0)),   "r"(__float_as_uint(b1)));
}

__device__ __forceinline__ float gelu_exact(float x) {
    return 0.5f * x * (1.0f + erff(x * 0.70710678118654752f));
}

__device__ __forceinline__ void cp_async16(void* smem_dst, const void* gmem_src) {
    unsigned s = (unsigned)__cvta_generic_to_shared(smem_dst);
    asm volatile("cp.async.cg.shared.global [%0], [%1], 16;\n" :: "r"(s), "l"(gmem_src));
}
// 16B copy with runtime src-size (0 -> full zero-fill)
__device__ __forceinline__ void cp_async16_zf(void* smem_dst, const void* gmem_src, int srcbytes) {
    unsigned s = (unsigned)__cvta_generic_to_shared(smem_dst);
    asm volatile("cp.async.ca.shared.global [%0], [%1], 16, %2;\n"
                 :: "r"(s), "l"(gmem_src), "r"(srcbytes));
}
#define CP_COMMIT() asm volatile("cp.async.commit_group;\n" ::: "memory")
#define CP_WAIT1()  asm volatile("cp.async.wait_group 1;\n" ::: "memory")
#define CP_WAIT0()  asm volatile("cp.async.wait_group 0;\n" ::: "memory")

// ---------------------------------------------------------------------------
// Kernel 0a: build compacted active-cell list (dtype-sniffing)
// ---------------------------------------------------------------------------
__global__ void build_cells_kernel(const void* __restrict__ maskp) {
    __shared__ int s_float, s_byte;
    __shared__ int wsum[32];
    int tid = threadIdx.x;
    if (tid == 0) { s_float = 0; s_byte = 0; }
    __syncthreads();
    if (tid < 256) {
        unsigned w = ((const unsigned*)maskp)[tid];
        if (w == 0x3F800000u) atomicOr(&s_float, 1);
        else if (w > 1u)      atomicOr(&s_byte, 1);
    }
    __syncthreads();
    int active;
    if (s_float)      active = (((const float*)maskp)[tid] != 0.0f) ? 1 : 0;
    else if (s_byte)  active = (((const unsigned char*)maskp)[tid] != 0) ? 1 : 0;
    else              active = (((const int*)maskp)[tid] != 0) ? 1 : 0;

    unsigned bal = __ballot_sync(0xffffffffu, active);
    int lane = tid & 31, wid = tid >> 5;
    int pre = __popc(bal & ((1u << lane) - 1u));
    if (lane == 31) wsum[wid] = pre + active;
    __syncthreads();
    if (wid == 0) {
        int v = wsum[lane];
        #pragma unroll
        for (int off = 1; off < 32; off <<= 1) {
            int t = __shfl_up_sync(0xffffffffu, v, off);
            if (lane >= off) v += t;
        }
        wsum[lane] = v;
    }
    __syncthreads();
    int base = (wid == 0) ? 0 : wsum[wid - 1];
    if (active) g_cellList[base + pre] = tid;
    if (tid == 1023) g_cellCount = wsum[31];
}

// ---------------------------------------------------------------------------
// Kernel 0b: RNA-round MLP weights to tf32 once (keeps rel_err margin while
// cp.async stages them raw in the GEMM kernels)
// ---------------------------------------------------------------------------
__global__ void round_weights_kernel(const float* __restrict__ w1,
                                     const float* __restrict__ w2) {
    int i = blockIdx.x * 256 + threadIdx.x;
    if (i < CH * HID) {
        g_w1r[i] = tf32r(w1[i]);
        g_w2r[i] = tf32r(w2[i]);
    }
}

// ---------------------------------------------------------------------------
// Kernel 1: depthwise 7^3 conv on active cells.
// Channel-planar smem tile [ch16][y10][z10][x12] (x window f4-aligned at
// x0-4..x0+8), staged via cp.async zero-fill. Lane offsets 48z+96y mod 128
// are distinct per quarter-warp -> conflict-free LDS.128.
// 128 threads: (pair p:8) x (z:4) x (y:4); each thread: x-row of 4 outputs,
// 2 channels packed in FFMA2.
// ---------------------------------------------------------------------------
#define CONV_PLANES_B (16 * 1200 * 4)                 // 76800
#define CONV_WGT_B    (8 * 344 * 8)                   // 22016
#define CONV_SOUT_B   (64 * 16 * 4 + 64)              // 4160
#define CONV_SMEM     (CONV_PLANES_B + CONV_WGT_B + CONV_SOUT_B)

__global__ __launch_bounds__(128)
void conv_kernel(const float* __restrict__ x,
                 const float* __restrict__ dw_w,
                 const float* __restrict__ dw_b) {
    int cellSlot = blockIdx.x / 12;
    if (cellSlot >= g_cellCount) return;
    int pg   = blockIdx.x % 12;
    int cell = g_cellList[cellSlot];
    int b  = cell >> 9;
    int cz = (cell >> 6) & 7, cy = (cell >> 3) & 7, cx = cell & 7;
    int z0 = cz * 4, y0 = cy * 4, x0 = cx * 4;
    int c0 = pg * 16;

    extern __shared__ char sm[];
    float*  tile = (float*)sm;                          // [16][10][10][12]
    float2* wgt  = (float2*)(sm + CONV_PLANES_B);       // [8][344]
    float*  sOut = (float*)(sm + CONV_PLANES_B + CONV_WGT_B);

    int tid = threadIdx.x;
    const float* xb = x + (size_t)b * CH * SPAT;
    int xbase = x0 - 4;

    // ---- stage input planes: 4800 x cp.async.16 with OOB zero-fill ----
    // idx = ((ch*10 + yi)*10 + zi)*3 + k ; smem dst = idx*16 bytes
    for (int idx = tid; idx < 4800; idx += 128) {
        int k  = idx % 3;
        int t  = idx / 3;
        int zi = t % 10;
        int t2 = t / 10;
        int yi = t2 % 10;
        int ch = t2 / 10;
        int gz = z0 + zi - 3, gy = y0 + yi - 3, gx = xbase + 4 * k;
        bool ok = ((unsigned)gz < 32u) && ((unsigned)gy < 32u) && ((unsigned)gx <= 28u);
        const float* src = xb + (size_t)(c0 + ch) * SPAT
                         + (ok ? (gz * 1024 + gy * 32 + gx) : 0);
        cp_async16_zf((char*)tile + (size_t)idx * 16, src, ok ? 16 : 0);
    }
    CP_COMMIT();

    // ---- stage weights (pair-packed float2) ----
    for (int idx = tid; idx < 8 * KV; idx += 128) {
        int p = idx / KV;
        int t = idx - p * KV;
        wgt[p * 344 + t] = make_float2(dw_w[(c0 + 2 * p) * KV + t],
                                       dw_w[(c0 + 2 * p + 1) * KV + t]);
    }
    CP_WAIT0();
    __syncthreads();

    int p  = tid >> 4;        // channel pair 0..7
    int z  = (tid >> 2) & 3;  // out z 0..3
    int yy = tid & 3;         // out y 0..3
    float2 bias = make_float2(dw_b[c0 + 2 * p], dw_b[c0 + 2 * p + 1]);
    float2 acc0 = bias, acc1 = bias, acc2 = bias, acc3 = bias;

    const float*  pA = tile + (2 * p) * 1200;       // plane of channel 2p
    const float*  pB = pA + 1200;                   // plane of channel 2p+1
    const float2* wp = wgt + p * 344;

    for (int dz = 0; dz < 7; dz++) {
        for (int dy = 0; dy < 7; dy++) {
            int off = (yy + dy) * 120 + (z + dz) * 12;
            float4 a0 = *(const float4*)(pA + off);
            float4 a1 = *(const float4*)(pA + off + 4);
            float4 a2 = *(const float4*)(pA + off + 8);
            float4 b0 = *(const float4*)(pB + off);
            float4 b1 = *(const float4*)(pB + off + 4);
            float4 b2 = *(const float4*)(pB + off + 8);
            float aV[12] = {a0.x,a0.y,a0.z,a0.w, a1.x,a1.y,a1.z,a1.w, a2.x,a2.y,a2.z,a2.w};
            float bV[12] = {b0.x,b0.y,b0.z,b0.w, b1.x,b1.y,b1.z,b1.w, b2.x,b2.y,b2.z,b2.w};
            const float2* wr = wp + (dz * 7 + dy) * 7;
            #pragma unroll
            for (int dx = 0; dx < 7; dx++) {
                float2 w = wr[dx];
                acc0 = ffma2(make_float2(aV[dx + 1], bV[dx + 1]), w, acc0);
                acc1 = ffma2(make_float2(aV[dx + 2], bV[dx + 2]), w, acc1);
                acc2 = ffma2(make_float2(aV[dx + 3], bV[dx + 3]), w, acc2);
                acc3 = ffma2(make_float2(aV[dx + 4], bV[dx + 4]), w, acc3);
            }
        }
    }

    // ---- transpose through smem, write compacted channels-last ----
    int widx = z * 16 + yy * 4;
    sOut[(widx + 0) * 16 + 2 * p] = acc0.x; sOut[(widx + 0) * 16 + 2 * p + 1] = acc0.y;
    sOut[(widx + 1) * 16 + 2 * p] = acc1.x; sOut[(widx + 1) * 16 + 2 * p + 1] = acc1.y;
    sOut[(widx + 2) * 16 + 2 * p] = acc2.x; sOut[(widx + 2) * 16 + 2 * p + 1] = acc2.y;
    sOut[(widx + 3) * 16 + 2 * p] = acc3.x; sOut[(widx + 3) * 16 + 2 * p + 1] = acc3.y;
    __syncthreads();

    float* yout = g_yc + (size_t)cellSlot * CELLTOK * CH + c0;
    #pragma unroll
    for (int k = 0; k < 8; k++) {
        int i  = k * 128 + tid;
        int w  = i >> 4;
        int ch = i & 15;
        yout[(size_t)w * CH + ch] = sOut[w * 16 + ch];
    }
}

// ---------------------------------------------------------------------------
// Kernel 2: LayerNorm + GEMM1 + gelu -> g_h (unchanged from round 4 except
// it now stages pre-rounded g_w1r).
// ---------------------------------------------------------------------------
#define SY1   196
#define SWB1  40
#define M1_OFF_W1 (64 * SY1)
#define M1_SMEM ((M1_OFF_W1 + 2 * 192 * SWB1) * 4)

__global__ __launch_bounds__(256)
void mlp1_kernel(const float* __restrict__ ln_w, const float* __restrict__ ln_b,
                 const float* __restrict__ bias1) {
    int cellSlot = blockIdx.x;
    if (cellSlot >= g_cellCount) return;

    extern __shared__ float sm1[];
    float* sY = sm1;
    float* sW = sm1 + M1_OFF_W1;

    int tid = threadIdx.x;
    const float* w1 = g_w1r;

    for (int i = tid; i < 1536; i += 256) {
        int k = i >> 3, q = i & 7;
        cp_async16(&sW[k * SWB1 + q * 4], w1 + (size_t)k * HID + q * 4);
    }
    CP_COMMIT();

    const float* yrow = g_yc + (size_t)cellSlot * CELLTOK * CH;
    for (int i = tid; i < 64 * 48; i += 256) {
        int r = i / 48, cq = i - r * 48;
        float4 v = *(const float4*)(yrow + (size_t)r * CH + cq * 4);
        *(float4*)&sY[r * SY1 + cq * 4] = v;
    }
    __syncthreads();

    {
        int row = tid >> 2, q = tid & 3;
        float* ar = &sY[row * SY1 + q * 48];
        float s = 0.f, ss = 0.f;
        #pragma unroll
        for (int i = 0; i < 48; i++) { float v = ar[i]; s += v; ss += v * v; }
        s  += __shfl_xor_sync(0xffffffffu, s, 1);
        ss += __shfl_xor_sync(0xffffffffu, ss, 1);
        s  += __shfl_xor_sync(0xffffffffu, s, 2);
        ss += __shfl_xor_sync(0xffffffffu, ss, 2);
        float mu   = s * (1.0f / 192.0f);
        float var  = ss * (1.0f / 192.0f) - mu * mu;
        float rstd = rsqrtf(var + 1e-6f);
        #pragma unroll
        for (int i = 0; i < 48; i++) {
            int c = q * 48 + i;
            float v = (ar[i] - mu) * rstd * __ldg(ln_w + c) + __ldg(ln_b + c);
            ar[i] = tf32r(v);
        }
    }

    int wid = tid >> 5, lane = tid & 31;
    int g = lane >> 2, tg = lane & 3;
    int m0  = (wid >> 1) * 16;
    int nh1 = (wid & 1) * 16;
    float* hout = g_h + (size_t)cellSlot * CELLTOK * HID;

    for (int nc = 0; nc < 24; nc++) {
        if (nc + 1 < 24) {
            float* dst = sW + ((nc + 1) & 1) * 192 * SWB1;
            int n1 = (nc + 1) * 32;
            for (int i = tid; i < 1536; i += 256) {
                int k = i >> 3, q = i & 7;
                cp_async16(&dst[k * SWB1 + q * 4], w1 + (size_t)k * HID + n1 + q * 4);
            }
        }
        CP_COMMIT();
        CP_WAIT1();
        __syncthreads();

        const float* sB = sW + (nc & 1) * 192 * SWB1;
        float c1[2][4];
        #pragma unroll
        for (int s = 0; s < 2; s++)
            #pragma unroll
            for (int e = 0; e < 4; e++) c1[s][e] = 0.f;

        #pragma unroll 4
        for (int ks = 0; ks < 24; ks++) {
            int k0 = ks * 8;
            float av[4];
            av[0] = sY[(m0 + g) * SY1 + k0 + tg];
            av[1] = sY[(m0 + g + 8) * SY1 + k0 + tg];
            av[2] = sY[(m0 + g) * SY1 + k0 + tg + 4];
            av[3] = sY[(m0 + g + 8) * SY1 + k0 + tg + 4];
            #pragma unroll
            for (int sub = 0; sub < 2; sub++) {
                float bb0 = sB[(k0 + tg) * SWB1 + nh1 + sub * 8 + g];
                float bb1 = sB[(k0 + tg + 4) * SWB1 + nh1 + sub * 8 + g];
                mma_tf32(c1[sub], av, bb0, bb1);
            }
        }

        int n0 = nc * 32;
        #pragma unroll
        for (int sub = 0; sub < 2; sub++) {
            int n = n0 + nh1 + sub * 8 + 2 * tg;
            float bb0 = __ldg(bias1 + n), bb1 = __ldg(bias1 + n + 1);
            float2 v0 = make_float2(tf32r(gelu_exact(c1[sub][0] + bb0)),
                                    tf32r(gelu_exact(c1[sub][1] + bb1)));
            float2 v1 = make_float2(tf32r(gelu_exact(c1[sub][2] + bb0)),
                                    tf32r(gelu_exact(c1[sub][3] + bb1)));
            *(float2*)&hout[(size_t)(m0 + g) * HID + n]     = v0;
            *(float2*)&hout[(size_t)(m0 + g + 8) * HID + n] = v1;
        }
        __syncthreads();
    }
}

// ---------------------------------------------------------------------------
// Kernel 3: GEMM2 + b2 + gamma -> dense NCDHW scatter (stages g_w2r).
// ---------------------------------------------------------------------------
#define SA2   36
#define SB2   200
#define SO2   197
#define M2_OFF_B (2 * 64 * SA2)
#define M2_SMEM ((M2_OFF_B + 2 * 32 * SB2) * 4)

__global__ __launch_bounds__(256)
void mlp2_kernel(const float* __restrict__ bias2,
                 const float* __restrict__ gamma, float* __restrict__ out) {
    int cellSlot = blockIdx.x;
    if (cellSlot >= g_cellCount) return;
    int cell = g_cellList[cellSlot];
    int b  = cell >> 9;
    int cz = (cell >> 6) & 7, cy = (cell >> 3) & 7, cx = cell & 7;
    int z0 = cz * 4, y0 = cy * 4, x0 = cx * 4;

    extern __shared__ float sm2[];
    float* sAb = sm2;
    float* sBb = sm2 + M2_OFF_B;
    float* sO  = sm2 + M2_OFF_B;

    int tid = threadIdx.x;
    const float* hrow = g_h + (size_t)cellSlot * CELLTOK * HID;
    const float* w2 = g_w2r;

    {
        for (int i = tid; i < 512; i += 256) {
            int r = i >> 3, kq = i & 7;
            cp_async16(&sAb[r * SA2 + kq * 4], hrow + (size_t)r * HID + kq * 4);
        }
        for (int i = tid; i < 1536; i += 256) {
            int k = i / 48, q = i - k * 48;
            cp_async16(&sBb[k * SB2 + q * 4], w2 + (size_t)k * CH + q * 4);
        }
        CP_COMMIT();
    }

    int wid = tid >> 5, lane = tid & 31;
    int g = lane >> 2, tg = lane & 3;
    int m0  = (wid >> 1) * 16;
    int nh2 = (wid & 1) * 96;

    float acc[12][4];
    #pragma unroll
    for (int s = 0; s < 12; s++)
        #pragma unroll
        for (int e = 0; e < 4; e++) acc[s][e] = 0.f;

    for (int kc = 0; kc < 24; kc++) {
        if (kc + 1 < 24) {
            int kb = (kc + 1) * 32;
            float* dA = sAb + ((kc + 1) & 1) * 64 * SA2;
            float* dB = sBb + ((kc + 1) & 1) * 32 * SB2;
            for (int i = tid; i < 512; i += 256) {
                int r = i >> 3, kq = i & 7;
                cp_async16(&dA[r * SA2 + kq * 4], hrow + (size_t)r * HID + kb + kq * 4);
            }
            for (int i = tid; i < 1536; i += 256) {
                int k = i / 48, q = i - k * 48;
                cp_async16(&dB[k * SB2 + q * 4], w2 + (size_t)(kb + k) * CH + q * 4);
            }
        }
        CP_COMMIT();
        CP_WAIT1();
        __syncthreads();

        const float* sA = sAb + (kc & 1) * 64 * SA2;
        const float* sB = sBb + (kc & 1) * 32 * SB2;

        #pragma unroll
        for (int ks = 0; ks < 4; ks++) {
            int k0 = ks * 8;
            float av[4];
            av[0] = sA[(m0 + g) * SA2 + k0 + tg];
            av[1] = sA[(m0 + g + 8) * SA2 + k0 + tg];
            av[2] = sA[(m0 + g) * SA2 + k0 + tg + 4];
            av[3] = sA[(m0 + g + 8) * SA2 + k0 + tg + 4];
            #pragma unroll
            for (int sub = 0; sub < 12; sub++) {
                float bb0 = sB[(k0 + tg) * SB2 + nh2 + sub * 8 + g];
                float bb1 = sB[(k0 + tg + 4) * SB2 + nh2 + sub * 8 + g];
                mma_tf32(acc[sub], av, bb0, bb1);
            }
        }
        __syncthreads();
    }

    #pragma unroll
    for (int sub = 0; sub < 12; sub++) {
        int n = nh2 + sub * 8 + 2 * tg;
        float g0 = __ldg(gamma + n), g1 = __ldg(gamma + n + 1);
        float bb0 = __ldg(bias2 + n), bb1 = __ldg(bias2 + n + 1);
        sO[(m0 + g) * SO2 + n]         = g0 * (acc[sub][0] + bb0);
        sO[(m0 + g) * SO2 + n + 1]     = g1 * (acc[sub][1] + bb1);
        sO[(m0 + g + 8) * SO2 + n]     = g0 * (acc[sub][2] + bb0);
        sO[(m0 + g + 8) * SO2 + n + 1] = g1 * (acc[sub][3] + bb1);
    }
    __syncthreads();

    for (int i = tid; i < 3072; i += 256) {
        int c = i >> 4, r = i & 15;
        int z = r >> 2, y = r & 3;
        int tok = z * 16 + y * 4;
        float4 v;
        v.x = sO[(tok + 0) * SO2 + c];
        v.y = sO[(tok + 1) * SO2 + c];
        v.z = sO[(tok + 2) * SO2 + c];
        v.w = sO[(tok + 3) * SO2 + c];
        size_t off = ((size_t)(b * CH + c)) * SPAT + (size_t)(z0 + z) * 1024
                   + (size_t)(y0 + y) * 32 + x0;
        *(float4*)(out + off) = v;
    }
}

// ---------------------------------------------------------------------------
// Launch
// ---------------------------------------------------------------------------
extern "C" void kernel_launch(void* const* d_in, const int* in_sizes, int n_in,
                              void* d_out, int out_size) {
    const float* x     = (const float*)d_in[0];
    const void*  mask  = d_in[1];
    const float* dw_w  = (const float*)d_in[2];
    const float* dw_b  = (const float*)d_in[3];
    const float* ln_w  = (const float*)d_in[4];
    const float* ln_b  = (const float*)d_in[5];
    const float* w1    = (const float*)d_in[6];
    const float* b1    = (const float*)d_in[7];
    const float* w2    = (const float*)d_in[8];
    const float* b2    = (const float*)d_in[9];
    const float* gamma = (const float*)d_in[10];
    float* out = (float*)d_out;

    cudaFuncSetAttribute(conv_kernel, cudaFuncAttributeMaxDynamicSharedMemorySize, CONV_SMEM);
    cudaFuncSetAttribute(mlp1_kernel, cudaFuncAttributeMaxDynamicSharedMemorySize, M1_SMEM);
    cudaFuncSetAttribute(mlp2_kernel, cudaFuncAttributeMaxDynamicSharedMemorySize, M2_SMEM);

    cudaMemsetAsync(d_out, 0, (size_t)out_size * sizeof(float));
    build_cells_kernel<<<1, 1024>>>(mask);
    round_weights_kernel<<<(CH * HID + 255) / 256, 256>>>(w1, w2);
    conv_kernel<<<NCELLS * 12, 128, CONV_SMEM>>>(x, dw_w, dw_b);
    mlp1_kernel<<<NCELLS, 256, M1_SMEM>>>(ln_w, ln_b, b1);
    mlp2_kernel<<<NCELLS, 256, M2_SMEM>>>(b2, gamma, out);
}

// round 7
// speedup vs baseline: 1.1286x; 1.1286x over previous
#include <cuda_runtime.h>
#include <cuda_bf16.h>
#include <math.h>
#include <stdint.h>

// ---------------------------------------------------------------------------
// Problem constants
// ---------------------------------------------------------------------------
#define BATCH   2
#define CH      192
#define DIM     32
#define SPAT    (DIM*DIM*DIM)      // 32768
#define HID     768
#define KS      7
#define KV      343
#define NCELLS  1024               // 2 * 8*8*8
#define CELLTOK 64                 // 4*4*4

// ---------------------------------------------------------------------------
// Device scratch (static globals -- no runtime allocation)
// ---------------------------------------------------------------------------
__device__ int   g_cellList[NCELLS];
__device__ int   g_cellCount;
__device__ float g_yc[(size_t)NCELLS * CELLTOK * CH];    // compacted conv out
__device__ float g_h [(size_t)NCELLS * CELLTOK * HID];   // hidden activations
__device__ float g_w1r[CH * HID];                        // tf32-rounded w1
__device__ float g_w2r[HID * CH];                        // tf32-rounded w2

// ---------------------------------------------------------------------------
// Helpers
// ---------------------------------------------------------------------------
__device__ __forceinline__ float2 ffma2(float2 a, float2 b, float2 c) {
    union U { float2 f; unsigned long long u; };
    U A, B, C, D;
    A.f = a; B.f = b; C.f = c;
    asm("fma.rn.f32x2 %0, %1, %2, %3;" : "=l"(D.u) : "l"(A.u), "l"(B.u), "l"(C.u));
    return D.f;
}

__device__ __forceinline__ float tf32r(float x) {
    unsigned int u;
    asm("cvt.rna.tf32.f32 %0, %1;" : "=r"(u) : "f"(x));
    return __uint_as_float(u);
}

// mma.sync m16n8k8 tf32: d += a * b   (mapping verified by passing rounds)
__device__ __forceinline__ void mma_tf32(float* d, const float* a, float b0, float b1) {
    asm volatile(
        "mma.sync.aligned.m16n8k8.row.col.f32.tf32.tf32.f32 "
        "{%0,%1,%2,%3}, {%4,%5,%6,%7}, {%8,%9}, {%0,%1,%2,%3};"
        : "+f"(d[0]), "+f"(d[1]), "+f"(d[2]), "+f"(d[3])
        : "r"(__float_as_uint(a[0])), "r"(__float_as_uint(a[1])),
          "r"(__float_as_uint(a[2])), "r"(__float_as_uint(a[3])),
          "r"(__float_as_uint(b0)),   "r"(__float_as_uint(b1)));
}

__device__ __forceinline__ float gelu_exact(float x) {
    return 0.5f * x * (1.0f + erff(x * 0.70710678118654752f));
}

__device__ __forceinline__ void cp_async16(void* smem_dst, const void* gmem_src) {
    unsigned s = (unsigned)__cvta_generic_to_shared(smem_dst);
    asm volatile("cp.async.cg.shared.global [%0], [%1], 16;\n" :: "r"(s), "l"(gmem_src));
}
#define CP_COMMIT() asm volatile("cp.async.commit_group;\n" ::: "memory")
#define CP_WAIT1()  asm volatile("cp.async.wait_group 1;\n" ::: "memory")

// ---------------------------------------------------------------------------
// Kernel 0a: build compacted active-cell list (dtype-sniffing)
// ---------------------------------------------------------------------------
__global__ void build_cells_kernel(const void* __restrict__ maskp) {
    __shared__ int s_float, s_byte;
    __shared__ int wsum[32];
    int tid = threadIdx.x;
    if (tid == 0) { s_float = 0; s_byte = 0; }
    __syncthreads();
    if (tid < 256) {
        unsigned w = ((const unsigned*)maskp)[tid];
        if (w == 0x3F800000u) atomicOr(&s_float, 1);
        else if (w > 1u)      atomicOr(&s_byte, 1);
    }
    __syncthreads();
    int active;
    if (s_float)      active = (((const float*)maskp)[tid] != 0.0f) ? 1 : 0;
    else if (s_byte)  active = (((const unsigned char*)maskp)[tid] != 0) ? 1 : 0;
    else              active = (((const int*)maskp)[tid] != 0) ? 1 : 0;

    unsigned bal = __ballot_sync(0xffffffffu, active);
    int lane = tid & 31, wid = tid >> 5;
    int pre = __popc(bal & ((1u << lane) - 1u));
    if (lane == 31) wsum[wid] = pre + active;
    __syncthreads();
    if (wid == 0) {
        int v = wsum[lane];
        #pragma unroll
        for (int off = 1; off < 32; off <<= 1) {
            int t = __shfl_up_sync(0xffffffffu, v, off);
            if (lane >= off) v += t;
        }
        wsum[lane] = v;
    }
    __syncthreads();
    int base = (wid == 0) ? 0 : wsum[wid - 1];
    if (active) g_cellList[base + pre] = tid;
    if (tid == 1023) g_cellCount = wsum[31];
}

// ---------------------------------------------------------------------------
// Kernel 0b: RNA-round MLP weights to tf32 once
// ---------------------------------------------------------------------------
__global__ void round_weights_kernel(const float* __restrict__ w1,
                                     const float* __restrict__ w2) {
    int i = blockIdx.x * 256 + threadIdx.x;
    if (i < CH * HID) {
        g_w1r[i] = tf32r(w1[i]);
        g_w2r[i] = tf32r(w2[i]);
    }
}

// ---------------------------------------------------------------------------
// Kernel 1: depthwise 7^3 conv on active cells (round-4 proven version:
// float2-packed channel pairs, FFMA2, smem transpose epilogue)
// ---------------------------------------------------------------------------
#define CONV_TILE_F2 1200
#define CONV_TILE_B  (8 * CONV_TILE_F2 * 8)
#define CONV_WGT_B   (8 * 344 * 8)
#define CONV_SOUT_B  (64 * 16 * 4)
#define CONV_SMEM    (CONV_TILE_B + CONV_WGT_B + CONV_SOUT_B)

__global__ __launch_bounds__(128)
void conv_kernel(const float* __restrict__ x,
                 const float* __restrict__ dw_w,
                 const float* __restrict__ dw_b) {
    int cellSlot = blockIdx.x / 12;
    if (cellSlot >= g_cellCount) return;
    int pg   = blockIdx.x % 12;
    int cell = g_cellList[cellSlot];
    int b  = cell >> 9;
    int cz = (cell >> 6) & 7, cy = (cell >> 3) & 7, cx = cell & 7;
    int z0 = cz * 4, y0 = cy * 4, x0 = cx * 4;
    int c0 = pg * 16;

    extern __shared__ char sm[];
    float2* tile = (float2*)sm;
    float2* wgt  = (float2*)(sm + CONV_TILE_B);
    float*  sOut = (float*)(sm + CONV_TILE_B + CONV_WGT_B);

    int tid = threadIdx.x;
    const float* xb = x + (size_t)b * CH * SPAT;

    for (int idx = tid; idx < 8 * 1000; idx += 128) {
        int p  = idx / 1000;
        int s  = idx - p * 1000;
        int zi = s / 100;
        int r  = s - zi * 100;
        int yi = r / 10;
        int xi = r - yi * 10;
        int gz = z0 + zi - 3, gy = y0 + yi - 3, gx = x0 + xi - 3;
        float v0 = 0.f, v1 = 0.f;
        if (gz >= 0 && gz < DIM && gy >= 0 && gy < DIM && gx >= 0 && gx < DIM) {
            size_t off = (size_t)(c0 + 2 * p) * SPAT + gz * 1024 + gy * 32 + gx;
            v0 = xb[off];
            v1 = xb[off + SPAT];
        }
        tile[p * CONV_TILE_F2 + (zi * 10 + yi) * 12 + xi] = make_float2(v0, v1);
    }
    for (int idx = tid; idx < 8 * KV; idx += 128) {
        int p = idx / KV;
        int t = idx - p * KV;
        wgt[p * 344 + t] = make_float2(dw_w[(c0 + 2 * p) * KV + t],
                                       dw_w[(c0 + 2 * p + 1) * KV + t]);
    }
    __syncthreads();

    int p  = tid >> 4;
    int z  = (tid >> 2) & 3;
    int yy = tid & 3;
    float2 bias = make_float2(dw_b[c0 + 2 * p], dw_b[c0 + 2 * p + 1]);
    float2 acc0 = bias, acc1 = bias, acc2 = bias, acc3 = bias;

    const float2* tp = tile + p * CONV_TILE_F2;
    const float2* wp = wgt + p * 344;

    for (int dz = 0; dz < 7; dz++) {
        for (int dy = 0; dy < 7; dy++) {
            const float2* row = tp + ((z + dz) * 10 + (yy + dy)) * 12;
            float4 q0 = *(const float4*)(row + 0);
            float4 q1 = *(const float4*)(row + 2);
            float4 q2 = *(const float4*)(row + 4);
            float4 q3 = *(const float4*)(row + 6);
            float4 q4 = *(const float4*)(row + 8);
            float2 rr[10];
            rr[0] = make_float2(q0.x, q0.y); rr[1] = make_float2(q0.z, q0.w);
            rr[2] = make_float2(q1.x, q1.y); rr[3] = make_float2(q1.z, q1.w);
            rr[4] = make_float2(q2.x, q2.y); rr[5] = make_float2(q2.z, q2.w);
            rr[6] = make_float2(q3.x, q3.y); rr[7] = make_float2(q3.z, q3.w);
            rr[8] = make_float2(q4.x, q4.y); rr[9] = make_float2(q4.z, q4.w);
            const float2* wr = wp + (dz * 7 + dy) * 7;
            #pragma unroll
            for (int dx = 0; dx < 7; dx++) {
                float2 w = wr[dx];
                acc0 = ffma2(rr[dx + 0], w, acc0);
                acc1 = ffma2(rr[dx + 1], w, acc1);
                acc2 = ffma2(rr[dx + 2], w, acc2);
                acc3 = ffma2(rr[dx + 3], w, acc3);
            }
        }
    }

    int widx = z * 16 + yy * 4;
    sOut[(widx + 0) * 16 + 2 * p] = acc0.x; sOut[(widx + 0) * 16 + 2 * p + 1] = acc0.y;
    sOut[(widx + 1) * 16 + 2 * p] = acc1.x; sOut[(widx + 1) * 16 + 2 * p + 1] = acc1.y;
    sOut[(widx + 2) * 16 + 2 * p] = acc2.x; sOut[(widx + 2) * 16 + 2 * p + 1] = acc2.y;
    sOut[(widx + 3) * 16 + 2 * p] = acc3.x; sOut[(widx + 3) * 16 + 2 * p + 1] = acc3.y;
    __syncthreads();

    float* yout = g_yc + (size_t)cellSlot * CELLTOK * CH + c0;
    #pragma unroll
    for (int k = 0; k < 8; k++) {
        int i  = k * 128 + tid;
        int w  = i >> 4;
        int ch = i & 15;
        yout[(size_t)w * CH + ch] = sOut[w * 16 + ch];
    }
}

// ---------------------------------------------------------------------------
// Kernel 2: LayerNorm + GEMM1 + gelu -> g_h.
// HID-split x2: blockIdx.x = cellSlot*2 + half; each block does 384 cols
// in 6 N-chunks of 64. 256 thr = 8 warps (4M x 2N), each warp 32 cols
// (4 sub-accumulators -> 4 independent mma chains).
// smem: sY[64][196] + sW1[2][192][72] = 160,768 B
// Strides: 196 % 32 == 4 (A conflict-free), 72 % 32 == 8 (B conflict-free).
// ---------------------------------------------------------------------------
#define SY1   196
#define SWB1  72
#define M1_OFF_W1 (64 * SY1)
#define M1_SMEM ((M1_OFF_W1 + 2 * 192 * SWB1) * 4)

__global__ __launch_bounds__(256)
void mlp1_kernel(const float* __restrict__ ln_w, const float* __restrict__ ln_b,
                 const float* __restrict__ bias1) {
    int cellSlot = blockIdx.x >> 1;
    if (cellSlot >= g_cellCount) return;
    int half = blockIdx.x & 1;
    int hbase = half * 384;

    extern __shared__ float sm1[];
    float* sY = sm1;
    float* sW = sm1 + M1_OFF_W1;

    int tid = threadIdx.x;
    const float* w1 = g_w1r;

    // prefetch W1 chunk 0 (192 x 64) into buf 0
    for (int i = tid; i < 3072; i += 256) {           // 192 rows x 16 vec4
        int k = i >> 4, q = i & 15;
        cp_async16(&sW[k * SWB1 + q * 4], w1 + (size_t)k * HID + hbase + q * 4);
    }
    CP_COMMIT();

    const float* yrow = g_yc + (size_t)cellSlot * CELLTOK * CH;
    for (int i = tid; i < 64 * 48; i += 256) {
        int r = i / 48, cq = i - r * 48;
        float4 v = *(const float4*)(yrow + (size_t)r * CH + cq * 4);
        *(float4*)&sY[r * SY1 + cq * 4] = v;
    }
    __syncthreads();

    // LayerNorm (4 threads per token row) + tf32 round in place
    {
        int row = tid >> 2, q = tid & 3;
        float* ar = &sY[row * SY1 + q * 48];
        float s = 0.f, ss = 0.f;
        #pragma unroll
        for (int i = 0; i < 48; i++) { float v = ar[i]; s += v; ss += v * v; }
        s  += __shfl_xor_sync(0xffffffffu, s, 1);
        ss += __shfl_xor_sync(0xffffffffu, ss, 1);
        s  += __shfl_xor_sync(0xffffffffu, s, 2);
        ss += __shfl_xor_sync(0xffffffffu, ss, 2);
        float mu   = s * (1.0f / 192.0f);
        float var  = ss * (1.0f / 192.0f) - mu * mu;
        float rstd = rsqrtf(var + 1e-6f);
        #pragma unroll
        for (int i = 0; i < 48; i++) {
            int c = q * 48 + i;
            float v = (ar[i] - mu) * rstd * __ldg(ln_w + c) + __ldg(ln_b + c);
            ar[i] = tf32r(v);
        }
    }

    int wid = tid >> 5, lane = tid & 31;
    int g = lane >> 2, tg = lane & 3;
    int m0  = (wid >> 1) * 16;
    int nh1 = (wid & 1) * 32;
    float* hout = g_h + (size_t)cellSlot * CELLTOK * HID;

    for (int nc = 0; nc < 6; nc++) {
        if (nc + 1 < 6) {
            float* dst = sW + ((nc + 1) & 1) * 192 * SWB1;
            int n1 = hbase + (nc + 1) * 64;
            for (int i = tid; i < 3072; i += 256) {
                int k = i >> 4, q = i & 15;
                cp_async16(&dst[k * SWB1 + q * 4], w1 + (size_t)k * HID + n1 + q * 4);
            }
        }
        CP_COMMIT();
        CP_WAIT1();
        __syncthreads();

        const float* sB = sW + (nc & 1) * 192 * SWB1;
        float c1[4][4];
        #pragma unroll
        for (int s = 0; s < 4; s++)
            #pragma unroll
            for (int e = 0; e < 4; e++) c1[s][e] = 0.f;

        #pragma unroll 4
        for (int ks = 0; ks < 24; ks++) {
            int k0 = ks * 8;
            float av[4];
            av[0] = sY[(m0 + g) * SY1 + k0 + tg];
            av[1] = sY[(m0 + g + 8) * SY1 + k0 + tg];
            av[2] = sY[(m0 + g) * SY1 + k0 + tg + 4];
            av[3] = sY[(m0 + g + 8) * SY1 + k0 + tg + 4];
            #pragma unroll
            for (int sub = 0; sub < 4; sub++) {
                float bb0 = sB[(k0 + tg) * SWB1 + nh1 + sub * 8 + g];
                float bb1 = sB[(k0 + tg + 4) * SWB1 + nh1 + sub * 8 + g];
                mma_tf32(c1[sub], av, bb0, bb1);
            }
        }

        // epilogue: +b1, gelu, tf32 -> g_h (float2 stores)
        int n0 = hbase + nc * 64;
        #pragma unroll
        for (int sub = 0; sub < 4; sub++) {
            int n = n0 + nh1 + sub * 8 + 2 * tg;
            float bb0 = __ldg(bias1 + n), bb1 = __ldg(bias1 + n + 1);
            float2 v0 = make_float2(tf32r(gelu_exact(c1[sub][0] + bb0)),
                                    tf32r(gelu_exact(c1[sub][1] + bb1)));
            float2 v1 = make_float2(tf32r(gelu_exact(c1[sub][2] + bb0)),
                                    tf32r(gelu_exact(c1[sub][3] + bb1)));
            *(float2*)&hout[(size_t)(m0 + g) * HID + n]     = v0;
            *(float2*)&hout[(size_t)(m0 + g + 8) * HID + n] = v1;
        }
        __syncthreads();
    }
}

// ---------------------------------------------------------------------------
// Kernel 3: GEMM2 + b2 + gamma -> dense NCDHW scatter (stages g_w2r).
// ---------------------------------------------------------------------------
#define SA2   36
#define SB2   200
#define SO2   197
#define M2_OFF_B (2 * 64 * SA2)
#define M2_SMEM ((M2_OFF_B + 2 * 32 * SB2) * 4)

__global__ __launch_bounds__(256)
void mlp2_kernel(const float* __restrict__ bias2,
                 const float* __restrict__ gamma, float* __restrict__ out) {
    int cellSlot = blockIdx.x;
    if (cellSlot >= g_cellCount) return;
    int cell = g_cellList[cellSlot];
    int b  = cell >> 9;
    int cz = (cell >> 6) & 7, cy = (cell >> 3) & 7, cx = cell & 7;
    int z0 = cz * 4, y0 = cy * 4, x0 = cx * 4;

    extern __shared__ float sm2[];
    float* sAb = sm2;
    float* sBb = sm2 + M2_OFF_B;
    float* sO  = sm2 + M2_OFF_B;

    int tid = threadIdx.x;
    const float* hrow = g_h + (size_t)cellSlot * CELLTOK * HID;
    const float* w2 = g_w2r;

    {
        for (int i = tid; i < 512; i += 256) {
            int r = i >> 3, kq = i & 7;
            cp_async16(&sAb[r * SA2 + kq * 4], hrow + (size_t)r * HID + kq * 4);
        }
        for (int i = tid; i < 1536; i += 256) {
            int k = i / 48, q = i - k * 48;
            cp_async16(&sBb[k * SB2 + q * 4], w2 + (size_t)k * CH + q * 4);
        }
        CP_COMMIT();
    }

    int wid = tid >> 5, lane = tid & 31;
    int g = lane >> 2, tg = lane & 3;
    int m0  = (wid >> 1) * 16;
    int nh2 = (wid & 1) * 96;

    float acc[12][4];
    #pragma unroll
    for (int s = 0; s < 12; s++)
        #pragma unroll
        for (int e = 0; e < 4; e++) acc[s][e] = 0.f;

    for (int kc = 0; kc < 24; kc++) {
        if (kc + 1 < 24) {
            int kb = (kc + 1) * 32;
            float* dA = sAb + ((kc + 1) & 1) * 64 * SA2;
            float* dB = sBb + ((kc + 1) & 1) * 32 * SB2;
            for (int i = tid; i < 512; i += 256) {
                int r = i >> 3, kq = i & 7;
                cp_async16(&dA[r * SA2 + kq * 4], hrow + (size_t)r * HID + kb + kq * 4);
            }
            for (int i = tid; i < 1536; i += 256) {
                int k = i / 48, q = i - k * 48;
                cp_async16(&dB[k * SB2 + q * 4], w2 + (size_t)(kb + k) * CH + q * 4);
            }
        }
        CP_COMMIT();
        CP_WAIT1();
        __syncthreads();

        const float* sA = sAb + (kc & 1) * 64 * SA2;
        const float* sB = sBb + (kc & 1) * 32 * SB2;

        #pragma unroll
        for (int ks = 0; ks < 4; ks++) {
            int k0 = ks * 8;
            float av[4];
            av[0] = sA[(m0 + g) * SA2 + k0 + tg];
            av[1] = sA[(m0 + g + 8) * SA2 + k0 + tg];
            av[2] = sA[(m0 + g) * SA2 + k0 + tg + 4];
            av[3] = sA[(m0 + g + 8) * SA2 + k0 + tg + 4];
            #pragma unroll
            for (int sub = 0; sub < 12; sub++) {
                float bb0 = sB[(k0 + tg) * SB2 + nh2 + sub * 8 + g];
                float bb1 = sB[(k0 + tg + 4) * SB2 + nh2 + sub * 8 + g];
                mma_tf32(acc[sub], av, bb0, bb1);
            }
        }
        __syncthreads();
    }

    #pragma unroll
    for (int sub = 0; sub < 12; sub++) {
        int n = nh2 + sub * 8 + 2 * tg;
        float g0 = __ldg(gamma + n), g1 = __ldg(gamma + n + 1);
        float bb0 = __ldg(bias2 + n), bb1 = __ldg(bias2 + n + 1);
        sO[(m0 + g) * SO2 + n]         = g0 * (acc[sub][0] + bb0);
        sO[(m0 + g) * SO2 + n + 1]     = g1 * (acc[sub][1] + bb1);
        sO[(m0 + g + 8) * SO2 + n]     = g0 * (acc[sub][2] + bb0);
        sO[(m0 + g + 8) * SO2 + n + 1] = g1 * (acc[sub][3] + bb1);
    }
    __syncthreads();

    for (int i = tid; i < 3072; i += 256) {
        int c = i >> 4, r = i & 15;
        int z = r >> 2, y = r & 3;
        int tok = z * 16 + y * 4;
        float4 v;
        v.x = sO[(tok + 0) * SO2 + c];
        v.y = sO[(tok + 1) * SO2 + c];
        v.z = sO[(tok + 2) * SO2 + c];
        v.w = sO[(tok + 3) * SO2 + c];
        size_t off = ((size_t)(b * CH + c)) * SPAT + (size_t)(z0 + z) * 1024
                   + (size_t)(y0 + y) * 32 + x0;
        *(float4*)(out + off) = v;
    }
}

// ---------------------------------------------------------------------------
// Launch
// ---------------------------------------------------------------------------
extern "C" void kernel_launch(void* const* d_in, const int* in_sizes, int n_in,
                              void* d_out, int out_size) {
    const float* x     = (const float*)d_in[0];
    const void*  mask  = d_in[1];
    const float* dw_w  = (const float*)d_in[2];
    const float* dw_b  = (const float*)d_in[3];
    const float* ln_w  = (const float*)d_in[4];
    const float* ln_b  = (const float*)d_in[5];
    const float* w1    = (const float*)d_in[6];
    const float* b1    = (const float*)d_in[7];
    const float* w2    = (const float*)d_in[8];
    const float* b2    = (const float*)d_in[9];
    const float* gamma = (const float*)d_in[10];
    float* out = (float*)d_out;

    cudaFuncSetAttribute(conv_kernel, cudaFuncAttributeMaxDynamicSharedMemorySize, CONV_SMEM);
    cudaFuncSetAttribute(mlp1_kernel, cudaFuncAttributeMaxDynamicSharedMemorySize, M1_SMEM);
    cudaFuncSetAttribute(mlp2_kernel, cudaFuncAttributeMaxDynamicSharedMemorySize, M2_SMEM);

    cudaMemsetAsync(d_out, 0, (size_t)out_size * sizeof(float));
    build_cells_kernel<<<1, 1024>>>(mask);
    round_weights_kernel<<<(CH * HID + 255) / 256, 256>>>(w1, w2);
    conv_kernel<<<NCELLS * 12, 128, CONV_SMEM>>>(x, dw_w, dw_b);
    mlp1_kernel<<<NCELLS * 2, 256, M1_SMEM>>>(ln_w, ln_b, b1);
    mlp2_kernel<<<NCELLS, 256, M2_SMEM>>>(b2, gamma, out);
}

// round 8
// speedup vs baseline: 1.2754x; 1.1301x over previous
#include <cuda_runtime.h>
#include <cuda_bf16.h>
#include <math.h>
#include <stdint.h>

// ---------------------------------------------------------------------------
// Problem constants
// ---------------------------------------------------------------------------
#define BATCH   2
#define CH      192
#define DIM     32
#define SPAT    (DIM*DIM*DIM)      // 32768
#define HID     768
#define KS      7
#define KV      343
#define NCELLS  1024               // 2 * 8*8*8
#define CELLTOK 64                 // 4*4*4

// ---------------------------------------------------------------------------
// Device scratch (static globals -- no runtime allocation)
// ---------------------------------------------------------------------------
__device__ int   g_cellList[NCELLS];
__device__ int   g_cellCount;
__device__ float g_yc[(size_t)NCELLS * CELLTOK * CH];    // compacted conv out
__device__ float g_ln[(size_t)NCELLS * CELLTOK * CH];    // LN'd (tf32) tokens
__device__ float g_h [(size_t)NCELLS * CELLTOK * HID];   // hidden activations
__device__ float g_w1r[CH * HID];                        // tf32-rounded w1
__device__ float g_w2r[HID * CH];                        // tf32-rounded w2

// ---------------------------------------------------------------------------
// Helpers
// ---------------------------------------------------------------------------
__device__ __forceinline__ float2 ffma2(float2 a, float2 b, float2 c) {
    union U { float2 f; unsigned long long u; };
    U A, B, C, D;
    A.f = a; B.f = b; C.f = c;
    asm("fma.rn.f32x2 %0, %1, %2, %3;" : "=l"(D.u) : "l"(A.u), "l"(B.u), "l"(C.u));
    return D.f;
}

__device__ __forceinline__ float tf32r(float x) {
    unsigned int u;
    asm("cvt.rna.tf32.f32 %0, %1;" : "=r"(u) : "f"(x));
    return __uint_as_float(u);
}

// mma.sync m16n8k8 tf32: d += a * b   (mapping verified by passing rounds)
__device__ __forceinline__ void mma_tf32(float* d, const float* a, float b0, float b1) {
    asm volatile(
        "mma.sync.aligned.m16n8k8.row.col.f32.tf32.tf32.f32 "
        "{%0,%1,%2,%3}, {%4,%5,%6,%7}, {%8,%9}, {%0,%1,%2,%3};"
        : "+f"(d[0]), "+f"(d[1]), "+f"(d[2]), "+f"(d[3])
        : "r"(__float_as_uint(a[0])), "r"(__float_as_uint(a[1])),
          "r"(__float_as_uint(a[2])), "r"(__float_as_uint(a[3])),
          "r"(__float_as_uint(b0)),   "r"(__float_as_uint(b1)));
}

__device__ __forceinline__ float gelu_exact(float x) {
    return 0.5f * x * (1.0f + erff(x * 0.70710678118654752f));
}

__device__ __forceinline__ void cp_async16(void* smem_dst, const void* gmem_src) {
    unsigned s = (unsigned)__cvta_generic_to_shared(smem_dst);
    asm volatile("cp.async.cg.shared.global [%0], [%1], 16;\n" :: "r"(s), "l"(gmem_src));
}
#define CP_COMMIT() asm volatile("cp.async.commit_group;\n" ::: "memory")
#define CP_WAIT1()  asm volatile("cp.async.wait_group 1;\n" ::: "memory")

// ---------------------------------------------------------------------------
// Kernel 0a: build compacted active-cell list (dtype-sniffing)
// ---------------------------------------------------------------------------
__global__ void build_cells_kernel(const void* __restrict__ maskp) {
    __shared__ int s_float, s_byte;
    __shared__ int wsum[32];
    int tid = threadIdx.x;
    if (tid == 0) { s_float = 0; s_byte = 0; }
    __syncthreads();
    if (tid < 256) {
        unsigned w = ((const unsigned*)maskp)[tid];
        if (w == 0x3F800000u) atomicOr(&s_float, 1);
        else if (w > 1u)      atomicOr(&s_byte, 1);
    }
    __syncthreads();
    int active;
    if (s_float)      active = (((const float*)maskp)[tid] != 0.0f) ? 1 : 0;
    else if (s_byte)  active = (((const unsigned char*)maskp)[tid] != 0) ? 1 : 0;
    else              active = (((const int*)maskp)[tid] != 0) ? 1 : 0;

    unsigned bal = __ballot_sync(0xffffffffu, active);
    int lane = tid & 31, wid = tid >> 5;
    int pre = __popc(bal & ((1u << lane) - 1u));
    if (lane == 31) wsum[wid] = pre + active;
    __syncthreads();
    if (wid == 0) {
        int v = wsum[lane];
        #pragma unroll
        for (int off = 1; off < 32; off <<= 1) {
            int t = __shfl_up_sync(0xffffffffu, v, off);
            if (lane >= off) v += t;
        }
        wsum[lane] = v;
    }
    __syncthreads();
    int base = (wid == 0) ? 0 : wsum[wid - 1];
    if (active) g_cellList[base + pre] = tid;
    if (tid == 1023) g_cellCount = wsum[31];
}

// ---------------------------------------------------------------------------
// Kernel 0b: RNA-round MLP weights to tf32 once
// ---------------------------------------------------------------------------
__global__ void round_weights_kernel(const float* __restrict__ w1,
                                     const float* __restrict__ w2) {
    int i = blockIdx.x * 256 + threadIdx.x;
    if (i < CH * HID) {
        g_w1r[i] = tf32r(w1[i]);
        g_w2r[i] = tf32r(w2[i]);
    }
}

// ---------------------------------------------------------------------------
// Kernel 1: depthwise 7^3 conv on active cells.
// Round-4 structure; z-plane stride padded 120 -> 122 float2 so compute-phase
// LDS.128 is bank-conflict-free (976*dz + 96*dy != 0 mod 128 for all deltas).
// ---------------------------------------------------------------------------
#define CONV_TILE_F2 1220                          // 10 planes * 122 f2
#define CONV_TILE_B  (8 * CONV_TILE_F2 * 8)        // 78080
#define CONV_WGT_B   (8 * 344 * 8)                 // 22016
#define CONV_SOUT_B  (64 * 16 * 4)                 // 4096
#define CONV_SMEM    (CONV_TILE_B + CONV_WGT_B + CONV_SOUT_B)

__global__ __launch_bounds__(128)
void conv_kernel(const float* __restrict__ x,
                 const float* __restrict__ dw_w,
                 const float* __restrict__ dw_b) {
    int cellSlot = blockIdx.x / 12;
    if (cellSlot >= g_cellCount) return;
    int pg   = blockIdx.x % 12;
    int cell = g_cellList[cellSlot];
    int b  = cell >> 9;
    int cz = (cell >> 6) & 7, cy = (cell >> 3) & 7, cx = cell & 7;
    int z0 = cz * 4, y0 = cy * 4, x0 = cx * 4;
    int c0 = pg * 16;

    extern __shared__ char sm[];
    float2* tile = (float2*)sm;
    float2* wgt  = (float2*)(sm + CONV_TILE_B);
    float*  sOut = (float*)(sm + CONV_TILE_B + CONV_WGT_B);

    int tid = threadIdx.x;
    const float* xb = x + (size_t)b * CH * SPAT;

    for (int idx = tid; idx < 8 * 1000; idx += 128) {
        int p  = idx / 1000;
        int s  = idx - p * 1000;
        int zi = s / 100;
        int r  = s - zi * 100;
        int yi = r / 10;
        int xi = r - yi * 10;
        int gz = z0 + zi - 3, gy = y0 + yi - 3, gx = x0 + xi - 3;
        float v0 = 0.f, v1 = 0.f;
        if (gz >= 0 && gz < DIM && gy >= 0 && gy < DIM && gx >= 0 && gx < DIM) {
            size_t off = (size_t)(c0 + 2 * p) * SPAT + gz * 1024 + gy * 32 + gx;
            v0 = xb[off];
            v1 = xb[off + SPAT];
        }
        tile[p * CONV_TILE_F2 + zi * 122 + yi * 12 + xi] = make_float2(v0, v1);
    }
    for (int idx = tid; idx < 8 * KV; idx += 128) {
        int p = idx / KV;
        int t = idx - p * KV;
        wgt[p * 344 + t] = make_float2(dw_w[(c0 + 2 * p) * KV + t],
                                       dw_w[(c0 + 2 * p + 1) * KV + t]);
    }
    __syncthreads();

    int p  = tid >> 4;
    int z  = (tid >> 2) & 3;
    int yy = tid & 3;
    float2 bias = make_float2(dw_b[c0 + 2 * p], dw_b[c0 + 2 * p + 1]);
    float2 acc0 = bias, acc1 = bias, acc2 = bias, acc3 = bias;

    const float2* tp = tile + p * CONV_TILE_F2;
    const float2* wp = wgt + p * 344;

    for (int dz = 0; dz < 7; dz++) {
        for (int dy = 0; dy < 7; dy++) {
            const float2* row = tp + (z + dz) * 122 + (yy + dy) * 12;
            float4 q0 = *(const float4*)(row + 0);
            float4 q1 = *(const float4*)(row + 2);
            float4 q2 = *(const float4*)(row + 4);
            float4 q3 = *(const float4*)(row + 6);
            float4 q4 = *(const float4*)(row + 8);
            float2 rr[10];
            rr[0] = make_float2(q0.x, q0.y); rr[1] = make_float2(q0.z, q0.w);
            rr[2] = make_float2(q1.x, q1.y); rr[3] = make_float2(q1.z, q1.w);
            rr[4] = make_float2(q2.x, q2.y); rr[5] = make_float2(q2.z, q2.w);
            rr[6] = make_float2(q3.x, q3.y); rr[7] = make_float2(q3.z, q3.w);
            rr[8] = make_float2(q4.x, q4.y); rr[9] = make_float2(q4.z, q4.w);
            const float2* wr = wp + (dz * 7 + dy) * 7;
            #pragma unroll
            for (int dx = 0; dx < 7; dx++) {
                float2 w = wr[dx];
                acc0 = ffma2(rr[dx + 0], w, acc0);
                acc1 = ffma2(rr[dx + 1], w, acc1);
                acc2 = ffma2(rr[dx + 2], w, acc2);
                acc3 = ffma2(rr[dx + 3], w, acc3);
            }
        }
    }

    int widx = z * 16 + yy * 4;
    sOut[(widx + 0) * 16 + 2 * p] = acc0.x; sOut[(widx + 0) * 16 + 2 * p + 1] = acc0.y;
    sOut[(widx + 1) * 16 + 2 * p] = acc1.x; sOut[(widx + 1) * 16 + 2 * p + 1] = acc1.y;
    sOut[(widx + 2) * 16 + 2 * p] = acc2.x; sOut[(widx + 2) * 16 + 2 * p + 1] = acc2.y;
    sOut[(widx + 3) * 16 + 2 * p] = acc3.x; sOut[(widx + 3) * 16 + 2 * p + 1] = acc3.y;
    __syncthreads();

    float* yout = g_yc + (size_t)cellSlot * CELLTOK * CH + c0;
    #pragma unroll
    for (int k = 0; k < 8; k++) {
        int i  = k * 128 + tid;
        int w  = i >> 4;
        int ch = i & 15;
        yout[(size_t)w * CH + ch] = sOut[w * 16 + ch];
    }
}

// ---------------------------------------------------------------------------
// Kernel 2a: standalone LayerNorm: g_yc -> g_ln (tf32-rounded).
// 4 threads per token row; 256 threads = 64 rows = 1 cell per block.
// ---------------------------------------------------------------------------
__global__ __launch_bounds__(256)
void ln_kernel(const float* __restrict__ ln_w, const float* __restrict__ ln_b) {
    int cellSlot = blockIdx.x;
    if (cellSlot >= g_cellCount) return;
    int tid = threadIdx.x;
    int row = tid >> 2, q = tid & 3;

    const float* yr = g_yc + (size_t)cellSlot * CELLTOK * CH + (size_t)row * CH + q * 48;
    float*       lr = g_ln + (size_t)cellSlot * CELLTOK * CH + (size_t)row * CH + q * 48;

    float v[48];
    #pragma unroll
    for (int i = 0; i < 12; i++)
        *(float4*)&v[i * 4] = *(const float4*)(yr + i * 4);

    float s = 0.f, ss = 0.f;
    #pragma unroll
    for (int i = 0; i < 48; i++) { s += v[i]; ss += v[i] * v[i]; }
    s  += __shfl_xor_sync(0xffffffffu, s, 1);
    ss += __shfl_xor_sync(0xffffffffu, ss, 1);
    s  += __shfl_xor_sync(0xffffffffu, s, 2);
    ss += __shfl_xor_sync(0xffffffffu, ss, 2);
    float mu   = s * (1.0f / 192.0f);
    float var  = ss * (1.0f / 192.0f) - mu * mu;
    float rstd = rsqrtf(var + 1e-6f);

    #pragma unroll
    for (int i = 0; i < 48; i++) {
        int c = q * 48 + i;
        v[i] = tf32r((v[i] - mu) * rstd * __ldg(ln_w + c) + __ldg(ln_b + c));
    }
    #pragma unroll
    for (int i = 0; i < 12; i++)
        *(float4*)(lr + i * 4) = *(const float4*)&v[i * 4];
}

// ---------------------------------------------------------------------------
// Kernel 2b: GEMM1 (mlp2-clone) + gelu -> g_h.
// Block = (cellSlot, quarter): M64 x N192 x K192. K chunks of 32,
// double-buffered cp.async. 256 thr = 8 warps (4M x 2N), 12 subs/warp.
// smem: sA[2][64][36] + sB[2][32][200] = 69,632 B  (3 blocks/SM)
// ---------------------------------------------------------------------------
#define SA2   36
#define SB2   200
#define SO2   197
#define M2_OFF_B (2 * 64 * SA2)
#define M2_SMEM ((M2_OFF_B + 2 * 32 * SB2) * 4)

__global__ __launch_bounds__(256)
void mlp1_kernel(const float* __restrict__ bias1) {
    int cellSlot = blockIdx.x >> 2;
    if (cellSlot >= g_cellCount) return;
    int n0 = (blockIdx.x & 3) * 192;

    extern __shared__ float sm1[];
    float* sAb = sm1;                  // two buffers of 64*36
    float* sBb = sm1 + M2_OFF_B;       // two buffers of 32*200

    int tid = threadIdx.x;
    const float* lnrow = g_ln + (size_t)cellSlot * CELLTOK * CH;
    const float* w1 = g_w1r;

    // prefetch K-chunk 0
    {
        for (int i = tid; i < 512; i += 256) {        // A: 64 rows x 8 vec4
            int r = i >> 3, kq = i & 7;
            cp_async16(&sAb[r * SA2 + kq * 4], lnrow + (size_t)r * CH + kq * 4);
        }
        for (int i = tid; i < 1536; i += 256) {       // B: 32 rows x 48 vec4
            int k = i / 48, q = i - k * 48;
            cp_async16(&sBb[k * SB2 + q * 4], w1 + (size_t)k * HID + n0 + q * 4);
        }
        CP_COMMIT();
    }

    int wid = tid >> 5, lane = tid & 31;
    int g = lane >> 2, tg = lane & 3;
    int m0  = (wid >> 1) * 16;
    int nh2 = (wid & 1) * 96;

    float acc[12][4];
    #pragma unroll
    for (int s = 0; s < 12; s++)
        #pragma unroll
        for (int e = 0; e < 4; e++) acc[s][e] = 0.f;

    for (int kc = 0; kc < 6; kc++) {
        if (kc + 1 < 6) {
            int kb = (kc + 1) * 32;
            float* dA = sAb + ((kc + 1) & 1) * 64 * SA2;
            float* dB = sBb + ((kc + 1) & 1) * 32 * SB2;
            for (int i = tid; i < 512; i += 256) {
                int r = i >> 3, kq = i & 7;
                cp_async16(&dA[r * SA2 + kq * 4], lnrow + (size_t)r * CH + kb + kq * 4);
            }
            for (int i = tid; i < 1536; i += 256) {
                int k = i / 48, q = i - k * 48;
                cp_async16(&dB[k * SB2 + q * 4], w1 + (size_t)(kb + k) * HID + n0 + q * 4);
            }
        }
        CP_COMMIT();
        CP_WAIT1();
        __syncthreads();

        const float* sA = sAb + (kc & 1) * 64 * SA2;
        const float* sB = sBb + (kc & 1) * 32 * SB2;

        #pragma unroll
        for (int ks = 0; ks < 4; ks++) {
            int k0 = ks * 8;
            float av[4];
            av[0] = sA[(m0 + g) * SA2 + k0 + tg];
            av[1] = sA[(m0 + g + 8) * SA2 + k0 + tg];
            av[2] = sA[(m0 + g) * SA2 + k0 + tg + 4];
            av[3] = sA[(m0 + g + 8) * SA2 + k0 + tg + 4];
            #pragma unroll
            for (int sub = 0; sub < 12; sub++) {
                float bb0 = sB[(k0 + tg) * SB2 + nh2 + sub * 8 + g];
                float bb1 = sB[(k0 + tg + 4) * SB2 + nh2 + sub * 8 + g];
                mma_tf32(acc[sub], av, bb0, bb1);
            }
        }
        __syncthreads();
    }

    // epilogue: +b1, gelu, tf32 -> g_h (float2 stores)
    float* hout = g_h + (size_t)cellSlot * CELLTOK * HID + n0;
    #pragma unroll
    for (int sub = 0; sub < 12; sub++) {
        int n = nh2 + sub * 8 + 2 * tg;
        float bb0 = __ldg(bias1 + n0 + n), bb1 = __ldg(bias1 + n0 + n + 1);
        float2 v0 = make_float2(tf32r(gelu_exact(acc[sub][0] + bb0)),
                                tf32r(gelu_exact(acc[sub][1] + bb1)));
        float2 v1 = make_float2(tf32r(gelu_exact(acc[sub][2] + bb0)),
                                tf32r(gelu_exact(acc[sub][3] + bb1)));
        *(float2*)&hout[(size_t)(m0 + g) * HID + n]     = v0;
        *(float2*)&hout[(size_t)(m0 + g + 8) * HID + n] = v1;
    }
}

// ---------------------------------------------------------------------------
// Kernel 3: GEMM2 + b2 + gamma -> dense NCDHW scatter (unchanged).
// ---------------------------------------------------------------------------
__global__ __launch_bounds__(256)
void mlp2_kernel(const float* __restrict__ bias2,
                 const float* __restrict__ gamma, float* __restrict__ out) {
    int cellSlot = blockIdx.x;
    if (cellSlot >= g_cellCount) return;
    int cell = g_cellList[cellSlot];
    int b  = cell >> 9;
    int cz = (cell >> 6) & 7, cy = (cell >> 3) & 7, cx = cell & 7;
    int z0 = cz * 4, y0 = cy * 4, x0 = cx * 4;

    extern __shared__ float sm2[];
    float* sAb = sm2;
    float* sBb = sm2 + M2_OFF_B;
    float* sO  = sm2 + M2_OFF_B;

    int tid = threadIdx.x;
    const float* hrow = g_h + (size_t)cellSlot * CELLTOK * HID;
    const float* w2 = g_w2r;

    {
        for (int i = tid; i < 512; i += 256) {
            int r = i >> 3, kq = i & 7;
            cp_async16(&sAb[r * SA2 + kq * 4], hrow + (size_t)r * HID + kq * 4);
        }
        for (int i = tid; i < 1536; i += 256) {
            int k = i / 48, q = i - k * 48;
            cp_async16(&sBb[k * SB2 + q * 4], w2 + (size_t)k * CH + q * 4);
        }
        CP_COMMIT();
    }

    int wid = tid >> 5, lane = tid & 31;
    int g = lane >> 2, tg = lane & 3;
    int m0  = (wid >> 1) * 16;
    int nh2 = (wid & 1) * 96;

    float acc[12][4];
    #pragma unroll
    for (int s = 0; s < 12; s++)
        #pragma unroll
        for (int e = 0; e < 4; e++) acc[s][e] = 0.f;

    for (int kc = 0; kc < 24; kc++) {
        if (kc + 1 < 24) {
            int kb = (kc + 1) * 32;
            float* dA = sAb + ((kc + 1) & 1) * 64 * SA2;
            float* dB = sBb + ((kc + 1) & 1) * 32 * SB2;
            for (int i = tid; i < 512; i += 256) {
                int r = i >> 3, kq = i & 7;
                cp_async16(&dA[r * SA2 + kq * 4], hrow + (size_t)r * HID + kb + kq * 4);
            }
            for (int i = tid; i < 1536; i += 256) {
                int k = i / 48, q = i - k * 48;
                cp_async16(&dB[k * SB2 + q * 4], w2 + (size_t)(kb + k) * CH + q * 4);
            }
        }
        CP_COMMIT();
        CP_WAIT1();
        __syncthreads();

        const float* sA = sAb + (kc & 1) * 64 * SA2;
        const float* sB = sBb + (kc & 1) * 32 * SB2;

        #pragma unroll
        for (int ks = 0; ks < 4; ks++) {
            int k0 = ks * 8;
            float av[4];
            av[0] = sA[(m0 + g) * SA2 + k0 + tg];
            av[1] = sA[(m0 + g + 8) * SA2 + k0 + tg];
            av[2] = sA[(m0 + g) * SA2 + k0 + tg + 4];
            av[3] = sA[(m0 + g + 8) * SA2 + k0 + tg + 4];
            #pragma unroll
            for (int sub = 0; sub < 12; sub++) {
                float bb0 = sB[(k0 + tg) * SB2 + nh2 + sub * 8 + g];
                float bb1 = sB[(k0 + tg + 4) * SB2 + nh2 + sub * 8 + g];
                mma_tf32(acc[sub], av, bb0, bb1);
            }
        }
        __syncthreads();
    }

    #pragma unroll
    for (int sub = 0; sub < 12; sub++) {
        int n = nh2 + sub * 8 + 2 * tg;
        float g0 = __ldg(gamma + n), g1 = __ldg(gamma + n + 1);
        float bb0 = __ldg(bias2 + n), bb1 = __ldg(bias2 + n + 1);
        sO[(m0 + g) * SO2 + n]         = g0 * (acc[sub][0] + bb0);
        sO[(m0 + g) * SO2 + n + 1]     = g1 * (acc[sub][1] + bb1);
        sO[(m0 + g + 8) * SO2 + n]     = g0 * (acc[sub][2] + bb0);
        sO[(m0 + g + 8) * SO2 + n + 1] = g1 * (acc[sub][3] + bb1);
    }
    __syncthreads();

    for (int i = tid; i < 3072; i += 256) {
        int c = i >> 4, r = i & 15;
        int z = r >> 2, y = r & 3;
        int tok = z * 16 + y * 4;
        float4 v;
        v.x = sO[(tok + 0) * SO2 + c];
        v.y = sO[(tok + 1) * SO2 + c];
        v.z = sO[(tok + 2) * SO2 + c];
        v.w = sO[(tok + 3) * SO2 + c];
        size_t off = ((size_t)(b * CH + c)) * SPAT + (size_t)(z0 + z) * 1024
                   + (size_t)(y0 + y) * 32 + x0;
        *(float4*)(out + off) = v;
    }
}

// ---------------------------------------------------------------------------
// Launch
// ---------------------------------------------------------------------------
extern "C" void kernel_launch(void* const* d_in, const int* in_sizes, int n_in,
                              void* d_out, int out_size) {
    const float* x     = (const float*)d_in[0];
    const void*  mask  = d_in[1];
    const float* dw_w  = (const float*)d_in[2];
    const float* dw_b  = (const float*)d_in[3];
    const float* ln_w  = (const float*)d_in[4];
    const float* ln_b  = (const float*)d_in[5];
    const float* w1    = (const float*)d_in[6];
    const float* b1    = (const float*)d_in[7];
    const float* w2    = (const float*)d_in[8];
    const float* b2    = (const float*)d_in[9];
    const float* gamma = (const float*)d_in[10];
    float* out = (float*)d_out;

    cudaFuncSetAttribute(conv_kernel, cudaFuncAttributeMaxDynamicSharedMemorySize, CONV_SMEM);
    cudaFuncSetAttribute(mlp1_kernel, cudaFuncAttributeMaxDynamicSharedMemorySize, M2_SMEM);
    cudaFuncSetAttribute(mlp2_kernel, cudaFuncAttributeMaxDynamicSharedMemorySize, M2_SMEM);

    cudaMemsetAsync(d_out, 0, (size_t)out_size * sizeof(float));
    build_cells_kernel<<<1, 1024>>>(mask);
    round_weights_kernel<<<(CH * HID + 255) / 256, 256>>>(w1, w2);
    conv_kernel<<<NCELLS * 12, 128, CONV_SMEM>>>(x, dw_w, dw_b);
    ln_kernel<<<NCELLS, 256>>>(ln_w, ln_b);
    mlp1_kernel<<<NCELLS * 4, 256, M2_SMEM>>>(b1);
    mlp2_kernel<<<NCELLS, 256, M2_SMEM>>>(b2, gamma, out);
}

// round 9
// speedup vs baseline: 1.6067x; 1.2598x over previous
#include <cuda_runtime.h>
#include <cuda_bf16.h>
#include <math.h>
#include <stdint.h>

// ---------------------------------------------------------------------------
// Problem constants
// ---------------------------------------------------------------------------
#define BATCH   2
#define CH      192
#define DIM     32
#define SPAT    (DIM*DIM*DIM)      // 32768
#define HID     768
#define KS      7
#define KV      343
#define NCELLS  1024               // 2 * 8*8*8
#define CELLTOK 64                 // 4*4*4

// ---------------------------------------------------------------------------
// Device scratch (static globals -- no runtime allocation)
// ---------------------------------------------------------------------------
__device__ int   g_cellList[NCELLS];
__device__ int   g_cellCount;
__device__ float g_yc[(size_t)NCELLS * CELLTOK * CH];    // compacted conv out
__device__ float g_ln[(size_t)NCELLS * CELLTOK * CH];    // LN'd (tf32) tokens
__device__ float g_h [(size_t)NCELLS * CELLTOK * HID];   // hidden activations
__device__ float g_w1r[CH * HID];                        // tf32-rounded w1
__device__ float g_w2r[HID * CH];                        // tf32-rounded w2

// ---------------------------------------------------------------------------
// Helpers
// ---------------------------------------------------------------------------
__device__ __forceinline__ float2 ffma2(float2 a, float2 b, float2 c) {
    union U { float2 f; unsigned long long u; };
    U A, B, C, D;
    A.f = a; B.f = b; C.f = c;
    asm("fma.rn.f32x2 %0, %1, %2, %3;" : "=l"(D.u) : "l"(A.u), "l"(B.u), "l"(C.u));
    return D.f;
}

__device__ __forceinline__ float tf32r(float x) {
    unsigned int u;
    asm("cvt.rna.tf32.f32 %0, %1;" : "=r"(u) : "f"(x));
    return __uint_as_float(u);
}

// mma.sync m16n8k8 tf32: d += a * b   (mapping verified by passing rounds)
__device__ __forceinline__ void mma_tf32(float* d, const float* a, float b0, float b1) {
    asm volatile(
        "mma.sync.aligned.m16n8k8.row.col.f32.tf32.tf32.f32 "
        "{%0,%1,%2,%3}, {%4,%5,%6,%7}, {%8,%9}, {%0,%1,%2,%3};"
        : "+f"(d[0]), "+f"(d[1]), "+f"(d[2]), "+f"(d[3])
        : "r"(__float_as_uint(a[0])), "r"(__float_as_uint(a[1])),
          "r"(__float_as_uint(a[2])), "r"(__float_as_uint(a[3])),
          "r"(__float_as_uint(b0)),   "r"(__float_as_uint(b1)));
}

__device__ __forceinline__ float gelu_exact(float x) {
    return 0.5f * x * (1.0f + erff(x * 0.70710678118654752f));
}

__device__ __forceinline__ void cp_async16(void* smem_dst, const void* gmem_src) {
    unsigned s = (unsigned)__cvta_generic_to_shared(smem_dst);
    asm volatile("cp.async.cg.shared.global [%0], [%1], 16;\n" :: "r"(s), "l"(gmem_src));
}
#define CP_COMMIT() asm volatile("cp.async.commit_group;\n" ::: "memory")
#define CP_WAIT1()  asm volatile("cp.async.wait_group 1;\n" ::: "memory")

// ---------------------------------------------------------------------------
// Kernel 0a: build compacted active-cell list (dtype-sniffing)
// ---------------------------------------------------------------------------
__global__ void build_cells_kernel(const void* __restrict__ maskp) {
    __shared__ int s_float, s_byte;
    __shared__ int wsum[32];
    int tid = threadIdx.x;
    if (tid == 0) { s_float = 0; s_byte = 0; }
    __syncthreads();
    if (tid < 256) {
        unsigned w = ((const unsigned*)maskp)[tid];
        if (w == 0x3F800000u) atomicOr(&s_float, 1);
        else if (w > 1u)      atomicOr(&s_byte, 1);
    }
    __syncthreads();
    int active;
    if (s_float)      active = (((const float*)maskp)[tid] != 0.0f) ? 1 : 0;
    else if (s_byte)  active = (((const unsigned char*)maskp)[tid] != 0) ? 1 : 0;
    else              active = (((const int*)maskp)[tid] != 0) ? 1 : 0;

    unsigned bal = __ballot_sync(0xffffffffu, active);
    int lane = tid & 31, wid = tid >> 5;
    int pre = __popc(bal & ((1u << lane) - 1u));
    if (lane == 31) wsum[wid] = pre + active;
    __syncthreads();
    if (wid == 0) {
        int v = wsum[lane];
        #pragma unroll
        for (int off = 1; off < 32; off <<= 1) {
            int t = __shfl_up_sync(0xffffffffu, v, off);
            if (lane >= off) v += t;
        }
        wsum[lane] = v;
    }
    __syncthreads();
    int base = (wid == 0) ? 0 : wsum[wid - 1];
    if (active) g_cellList[base + pre] = tid;
    if (tid == 1023) g_cellCount = wsum[31];
}

// ---------------------------------------------------------------------------
// Kernel 0b: RNA-round MLP weights to tf32 once
// ---------------------------------------------------------------------------
__global__ void round_weights_kernel(const float* __restrict__ w1,
                                     const float* __restrict__ w2) {
    int i = blockIdx.x * 256 + threadIdx.x;
    if (i < CH * HID) {
        g_w1r[i] = tf32r(w1[i]);
        g_w2r[i] = tf32r(w2[i]);
    }
}

// ---------------------------------------------------------------------------
// Kernel 1: depthwise 7^3 conv on active cells.
// Block = (1 cell) x (8 channels = 4 pairs), 128 threads:
//   p = tid>>5 (pair), dzh = (tid>>4)&1, z = (tid>>2)&3, yy = tid&3.
// Each thread accumulates dz in {dzh, dzh+2, ...}; partners (lane ^16)
// combine via shfl. 52 KB smem -> 4 blocks/SM (4 warps/SMSP).
// ---------------------------------------------------------------------------
#define CONV_TILE_F2 1220                          // 10 z-planes * 122
#define CONV_TILE_B  (4 * CONV_TILE_F2 * 8)        // 39040
#define CONV_WGT_B   (4 * 344 * 8)                 // 11008
#define CONV_SOUT_B  (64 * 8 * 4)                  // 2048
#define CONV_SMEM    (CONV_TILE_B + CONV_WGT_B + CONV_SOUT_B)

__global__ __launch_bounds__(128)
void conv_kernel(const float* __restrict__ x,
                 const float* __restrict__ dw_w,
                 const float* __restrict__ dw_b) {
    int cellSlot = blockIdx.x / 24;
    if (cellSlot >= g_cellCount) return;
    int pg   = blockIdx.x % 24;
    int cell = g_cellList[cellSlot];
    int b  = cell >> 9;
    int cz = (cell >> 6) & 7, cy = (cell >> 3) & 7, cx = cell & 7;
    int z0 = cz * 4, y0 = cy * 4, x0 = cx * 4;
    int c0 = pg * 8;

    extern __shared__ char sm[];
    float2* tile = (float2*)sm;                         // [4][10z][10y][12x]
    float2* wgt  = (float2*)(sm + CONV_TILE_B);         // [4][344]
    float*  sOut = (float*)(sm + CONV_TILE_B + CONV_WGT_B);  // [64][8]

    int tid = threadIdx.x;
    const float* xb = x + (size_t)b * CH * SPAT;

    // ---- stage input (4 pairs x 10x10x10), packed float2 ----
    for (int idx = tid; idx < 4 * 1000; idx += 128) {
        int p  = idx / 1000;
        int s  = idx - p * 1000;
        int zi = s / 100;
        int r  = s - zi * 100;
        int yi = r / 10;
        int xi = r - yi * 10;
        int gz = z0 + zi - 3, gy = y0 + yi - 3, gx = x0 + xi - 3;
        float v0 = 0.f, v1 = 0.f;
        if (gz >= 0 && gz < DIM && gy >= 0 && gy < DIM && gx >= 0 && gx < DIM) {
            size_t off = (size_t)(c0 + 2 * p) * SPAT + gz * 1024 + gy * 32 + gx;
            v0 = xb[off];
            v1 = xb[off + SPAT];
        }
        tile[p * CONV_TILE_F2 + zi * 122 + yi * 12 + xi] = make_float2(v0, v1);
    }
    for (int idx = tid; idx < 4 * KV; idx += 128) {
        int p = idx / KV;
        int t = idx - p * KV;
        wgt[p * 344 + t] = make_float2(dw_w[(c0 + 2 * p) * KV + t],
                                       dw_w[(c0 + 2 * p + 1) * KV + t]);
    }
    __syncthreads();

    int p   = tid >> 5;        // pair 0..3
    int dzh = (tid >> 4) & 1;  // dz parity
    int z   = (tid >> 2) & 3;  // out z
    int yy  = tid & 3;         // out y
    float2 acc0 = make_float2(0.f, 0.f), acc1 = acc0, acc2 = acc0, acc3 = acc0;

    const float2* tp = tile + p * CONV_TILE_F2;
    const float2* wp = wgt + p * 344;

    for (int dz = dzh; dz < 7; dz += 2) {
        for (int dy = 0; dy < 7; dy++) {
            const float2* row = tp + (z + dz) * 122 + (yy + dy) * 12;
            float4 q0 = *(const float4*)(row + 0);
            float4 q1 = *(const float4*)(row + 2);
            float4 q2 = *(const float4*)(row + 4);
            float4 q3 = *(const float4*)(row + 6);
            float4 q4 = *(const float4*)(row + 8);
            float2 rr[10];
            rr[0] = make_float2(q0.x, q0.y); rr[1] = make_float2(q0.z, q0.w);
            rr[2] = make_float2(q1.x, q1.y); rr[3] = make_float2(q1.z, q1.w);
            rr[4] = make_float2(q2.x, q2.y); rr[5] = make_float2(q2.z, q2.w);
            rr[6] = make_float2(q3.x, q3.y); rr[7] = make_float2(q3.z, q3.w);
            rr[8] = make_float2(q4.x, q4.y); rr[9] = make_float2(q4.z, q4.w);
            const float2* wr = wp + (dz * 7 + dy) * 7;
            #pragma unroll
            for (int dx = 0; dx < 7; dx++) {
                float2 w = wr[dx];
                acc0 = ffma2(rr[dx + 0], w, acc0);
                acc1 = ffma2(rr[dx + 1], w, acc1);
                acc2 = ffma2(rr[dx + 2], w, acc2);
                acc3 = ffma2(rr[dx + 3], w, acc3);
            }
        }
    }

    // ---- combine dz-parity halves (partner lane ^ 16, same warp) ----
    acc0.x += __shfl_xor_sync(0xffffffffu, acc0.x, 16);
    acc0.y += __shfl_xor_sync(0xffffffffu, acc0.y, 16);
    acc1.x += __shfl_xor_sync(0xffffffffu, acc1.x, 16);
    acc1.y += __shfl_xor_sync(0xffffffffu, acc1.y, 16);
    acc2.x += __shfl_xor_sync(0xffffffffu, acc2.x, 16);
    acc2.y += __shfl_xor_sync(0xffffffffu, acc2.y, 16);
    acc3.x += __shfl_xor_sync(0xffffffffu, acc3.x, 16);
    acc3.y += __shfl_xor_sync(0xffffffffu, acc3.y, 16);

    if (dzh == 0) {
        float2 bias = make_float2(dw_b[c0 + 2 * p], dw_b[c0 + 2 * p + 1]);
        acc0.x += bias.x; acc0.y += bias.y;
        acc1.x += bias.x; acc1.y += bias.y;
        acc2.x += bias.x; acc2.y += bias.y;
        acc3.x += bias.x; acc3.y += bias.y;
        int widx = z * 16 + yy * 4;
        sOut[(widx + 0) * 8 + 2 * p] = acc0.x; sOut[(widx + 0) * 8 + 2 * p + 1] = acc0.y;
        sOut[(widx + 1) * 8 + 2 * p] = acc1.x; sOut[(widx + 1) * 8 + 2 * p + 1] = acc1.y;
        sOut[(widx + 2) * 8 + 2 * p] = acc2.x; sOut[(widx + 2) * 8 + 2 * p + 1] = acc2.y;
        sOut[(widx + 3) * 8 + 2 * p] = acc3.x; sOut[(widx + 3) * 8 + 2 * p + 1] = acc3.y;
    }
    __syncthreads();

    // ---- write compacted channels-last: 64 tokens x 8 ch = 128 float4 ----
    {
        int tok  = tid >> 1;
        int half = tid & 1;
        float4 v = *(const float4*)&sOut[tok * 8 + half * 4];
        *(float4*)(g_yc + (size_t)cellSlot * CELLTOK * CH
                   + (size_t)tok * CH + c0 + half * 4) = v;
    }
}

// ---------------------------------------------------------------------------
// Kernel 2a: standalone LayerNorm: g_yc -> g_ln (tf32-rounded).
// ---------------------------------------------------------------------------
__global__ __launch_bounds__(256)
void ln_kernel(const float* __restrict__ ln_w, const float* __restrict__ ln_b) {
    int cellSlot = blockIdx.x;
    if (cellSlot >= g_cellCount) return;
    int tid = threadIdx.x;
    int row = tid >> 2, q = tid & 3;

    const float* yr = g_yc + (size_t)cellSlot * CELLTOK * CH + (size_t)row * CH + q * 48;
    float*       lr = g_ln + (size_t)cellSlot * CELLTOK * CH + (size_t)row * CH + q * 48;

    float v[48];
    #pragma unroll
    for (int i = 0; i < 12; i++)
        *(float4*)&v[i * 4] = *(const float4*)(yr + i * 4);

    float s = 0.f, ss = 0.f;
    #pragma unroll
    for (int i = 0; i < 48; i++) { s += v[i]; ss += v[i] * v[i]; }
    s  += __shfl_xor_sync(0xffffffffu, s, 1);
    ss += __shfl_xor_sync(0xffffffffu, ss, 1);
    s  += __shfl_xor_sync(0xffffffffu, s, 2);
    ss += __shfl_xor_sync(0xffffffffu, ss, 2);
    float mu   = s * (1.0f / 192.0f);
    float var  = ss * (1.0f / 192.0f) - mu * mu;
    float rstd = rsqrtf(var + 1e-6f);

    #pragma unroll
    for (int i = 0; i < 48; i++) {
        int c = q * 48 + i;
        v[i] = tf32r((v[i] - mu) * rstd * __ldg(ln_w + c) + __ldg(ln_b + c));
    }
    #pragma unroll
    for (int i = 0; i < 12; i++)
        *(float4*)(lr + i * 4) = *(const float4*)&v[i * 4];
}

// ---------------------------------------------------------------------------
// Kernel 2b: GEMM1 (mlp2-clone) + gelu -> g_h.   (unchanged from round 8)
// ---------------------------------------------------------------------------
#define SA2   36
#define SB2   200
#define SO2   197
#define M2_OFF_B (2 * 64 * SA2)
#define M2_SMEM ((M2_OFF_B + 2 * 32 * SB2) * 4)

__global__ __launch_bounds__(256)
void mlp1_kernel(const float* __restrict__ bias1) {
    int cellSlot = blockIdx.x >> 2;
    if (cellSlot >= g_cellCount) return;
    int n0 = (blockIdx.x & 3) * 192;

    extern __shared__ float sm1[];
    float* sAb = sm1;
    float* sBb = sm1 + M2_OFF_B;

    int tid = threadIdx.x;
    const float* lnrow = g_ln + (size_t)cellSlot * CELLTOK * CH;
    const float* w1 = g_w1r;

    {
        for (int i = tid; i < 512; i += 256) {
            int r = i >> 3, kq = i & 7;
            cp_async16(&sAb[r * SA2 + kq * 4], lnrow + (size_t)r * CH + kq * 4);
        }
        for (int i = tid; i < 1536; i += 256) {
            int k = i / 48, q = i - k * 48;
            cp_async16(&sBb[k * SB2 + q * 4], w1 + (size_t)k * HID + n0 + q * 4);
        }
        CP_COMMIT();
    }

    int wid = tid >> 5, lane = tid & 31;
    int g = lane >> 2, tg = lane & 3;
    int m0  = (wid >> 1) * 16;
    int nh2 = (wid & 1) * 96;

    float acc[12][4];
    #pragma unroll
    for (int s = 0; s < 12; s++)
        #pragma unroll
        for (int e = 0; e < 4; e++) acc[s][e] = 0.f;

    for (int kc = 0; kc < 6; kc++) {
        if (kc + 1 < 6) {
            int kb = (kc + 1) * 32;
            float* dA = sAb + ((kc + 1) & 1) * 64 * SA2;
            float* dB = sBb + ((kc + 1) & 1) * 32 * SB2;
            for (int i = tid; i < 512; i += 256) {
                int r = i >> 3, kq = i & 7;
                cp_async16(&dA[r * SA2 + kq * 4], lnrow + (size_t)r * CH + kb + kq * 4);
            }
            for (int i = tid; i < 1536; i += 256) {
                int k = i / 48, q = i - k * 48;
                cp_async16(&dB[k * SB2 + q * 4], w1 + (size_t)(kb + k) * HID + n0 + q * 4);
            }
        }
        CP_COMMIT();
        CP_WAIT1();
        __syncthreads();

        const float* sA = sAb + (kc & 1) * 64 * SA2;
        const float* sB = sBb + (kc & 1) * 32 * SB2;

        #pragma unroll
        for (int ks = 0; ks < 4; ks++) {
            int k0 = ks * 8;
            float av[4];
            av[0] = sA[(m0 + g) * SA2 + k0 + tg];
            av[1] = sA[(m0 + g + 8) * SA2 + k0 + tg];
            av[2] = sA[(m0 + g) * SA2 + k0 + tg + 4];
            av[3] = sA[(m0 + g + 8) * SA2 + k0 + tg + 4];
            #pragma unroll
            for (int sub = 0; sub < 12; sub++) {
                float bb0 = sB[(k0 + tg) * SB2 + nh2 + sub * 8 + g];
                float bb1 = sB[(k0 + tg + 4) * SB2 + nh2 + sub * 8 + g];
                mma_tf32(acc[sub], av, bb0, bb1);
            }
        }
        __syncthreads();
    }

    float* hout = g_h + (size_t)cellSlot * CELLTOK * HID + n0;
    #pragma unroll
    for (int sub = 0; sub < 12; sub++) {
        int n = nh2 + sub * 8 + 2 * tg;
        float bb0 = __ldg(bias1 + n0 + n), bb1 = __ldg(bias1 + n0 + n + 1);
        float2 v0 = make_float2(tf32r(gelu_exact(acc[sub][0] + bb0)),
                                tf32r(gelu_exact(acc[sub][1] + bb1)));
        float2 v1 = make_float2(tf32r(gelu_exact(acc[sub][2] + bb0)),
                                tf32r(gelu_exact(acc[sub][3] + bb1)));
        *(float2*)&hout[(size_t)(m0 + g) * HID + n]     = v0;
        *(float2*)&hout[(size_t)(m0 + g + 8) * HID + n] = v1;
    }
}

// ---------------------------------------------------------------------------
// Kernel 3: GEMM2 + b2 + gamma -> dense NCDHW scatter (unchanged).
// ---------------------------------------------------------------------------
__global__ __launch_bounds__(256)
void mlp2_kernel(const float* __restrict__ bias2,
                 const float* __restrict__ gamma, float* __restrict__ out) {
    int cellSlot = blockIdx.x;
    if (cellSlot >= g_cellCount) return;
    int cell = g_cellList[cellSlot];
    int b  = cell >> 9;
    int cz = (cell >> 6) & 7, cy = (cell >> 3) & 7, cx = cell & 7;
    int z0 = cz * 4, y0 = cy * 4, x0 = cx * 4;

    extern __shared__ float sm2[];
    float* sAb = sm2;
    float* sBb = sm2 + M2_OFF_B;
    float* sO  = sm2 + M2_OFF_B;

    int tid = threadIdx.x;
    const float* hrow = g_h + (size_t)cellSlot * CELLTOK * HID;
    const float* w2 = g_w2r;

    {
        for (int i = tid; i < 512; i += 256) {
            int r = i >> 3, kq = i & 7;
            cp_async16(&sAb[r * SA2 + kq * 4], hrow + (size_t)r * HID + kq * 4);
        }
        for (int i = tid; i < 1536; i += 256) {
            int k = i / 48, q = i - k * 48;
            cp_async16(&sBb[k * SB2 + q * 4], w2 + (size_t)k * CH + q * 4);
        }
        CP_COMMIT();
    }

    int wid = tid >> 5, lane = tid & 31;
    int g = lane >> 2, tg = lane & 3;
    int m0  = (wid >> 1) * 16;
    int nh2 = (wid & 1) * 96;

    float acc[12][4];
    #pragma unroll
    for (int s = 0; s < 12; s++)
        #pragma unroll
        for (int e = 0; e < 4; e++) acc[s][e] = 0.f;

    for (int kc = 0; kc < 24; kc++) {
        if (kc + 1 < 24) {
            int kb = (kc + 1) * 32;
            float* dA = sAb + ((kc + 1) & 1) * 64 * SA2;
            float* dB = sBb + ((kc + 1) & 1) * 32 * SB2;
            for (int i = tid; i < 512; i += 256) {
                int r = i >> 3, kq = i & 7;
                cp_async16(&dA[r * SA2 + kq * 4], hrow + (size_t)r * HID + kb + kq * 4);
            }
            for (int i = tid; i < 1536; i += 256) {
                int k = i / 48, q = i - k * 48;
                cp_async16(&dB[k * SB2 + q * 4], w2 + (size_t)(kb + k) * CH + q * 4);
            }
        }
        CP_COMMIT();
        CP_WAIT1();
        __syncthreads();

        const float* sA = sAb + (kc & 1) * 64 * SA2;
        const float* sB = sBb + (kc & 1) * 32 * SB2;

        #pragma unroll
        for (int ks = 0; ks < 4; ks++) {
            int k0 = ks * 8;
            float av[4];
            av[0] = sA[(m0 + g) * SA2 + k0 + tg];
            av[1] = sA[(m0 + g + 8) * SA2 + k0 + tg];
            av[2] = sA[(m0 + g) * SA2 + k0 + tg + 4];
            av[3] = sA[(m0 + g + 8) * SA2 + k0 + tg + 4];
            #pragma unroll
            for (int sub = 0; sub < 12; sub++) {
                float bb0 = sB[(k0 + tg) * SB2 + nh2 + sub * 8 + g];
                float bb1 = sB[(k0 + tg + 4) * SB2 + nh2 + sub * 8 + g];
                mma_tf32(acc[sub], av, bb0, bb1);
            }
        }
        __syncthreads();
    }

    #pragma unroll
    for (int sub = 0; sub < 12; sub++) {
        int n = nh2 + sub * 8 + 2 * tg;
        float g0 = __ldg(gamma + n), g1 = __ldg(gamma + n + 1);
        float bb0 = __ldg(bias2 + n), bb1 = __ldg(bias2 + n + 1);
        sO[(m0 + g) * SO2 + n]         = g0 * (acc[sub][0] + bb0);
        sO[(m0 + g) * SO2 + n + 1]     = g1 * (acc[sub][1] + bb1);
        sO[(m0 + g + 8) * SO2 + n]     = g0 * (acc[sub][2] + bb0);
        sO[(m0 + g + 8) * SO2 + n + 1] = g1 * (acc[sub][3] + bb1);
    }
    __syncthreads();

    for (int i = tid; i < 3072; i += 256) {
        int c = i >> 4, r = i & 15;
        int z = r >> 2, y = r & 3;
        int tok = z * 16 + y * 4;
        float4 v;
        v.x = sO[(tok + 0) * SO2 + c];
        v.y = sO[(tok + 1) * SO2 + c];
        v.z = sO[(tok + 2) * SO2 + c];
        v.w = sO[(tok + 3) * SO2 + c];
        size_t off = ((size_t)(b * CH + c)) * SPAT + (size_t)(z0 + z) * 1024
                   + (size_t)(y0 + y) * 32 + x0;
        *(float4*)(out + off) = v;
    }
}

// ---------------------------------------------------------------------------
// Launch
// ---------------------------------------------------------------------------
extern "C" void kernel_launch(void* const* d_in, const int* in_sizes, int n_in,
                              void* d_out, int out_size) {
    const float* x     = (const float*)d_in[0];
    const void*  mask  = d_in[1];
    const float* dw_w  = (const float*)d_in[2];
    const float* dw_b  = (const float*)d_in[3];
    const float* ln_w  = (const float*)d_in[4];
    const float* ln_b  = (const float*)d_in[5];
    const float* w1    = (const float*)d_in[6];
    const float* b1    = (const float*)d_in[7];
    const float* w2    = (const float*)d_in[8];
    const float* b2    = (const float*)d_in[9];
    const float* gamma = (const float*)d_in[10];
    float* out = (float*)d_out;

    cudaFuncSetAttribute(conv_kernel, cudaFuncAttributeMaxDynamicSharedMemorySize, CONV_SMEM);
    cudaFuncSetAttribute(mlp1_kernel, cudaFuncAttributeMaxDynamicSharedMemorySize, M2_SMEM);
    cudaFuncSetAttribute(mlp2_kernel, cudaFuncAttributeMaxDynamicSharedMemorySize, M2_SMEM);

    cudaMemsetAsync(d_out, 0, (size_t)out_size * sizeof(float));
    build_cells_kernel<<<1, 1024>>>(mask);
    round_weights_kernel<<<(CH * HID + 255) / 256, 256>>>(w1, w2);
    conv_kernel<<<NCELLS * 24, 128, CONV_SMEM>>>(x, dw_w, dw_b);
    ln_kernel<<<NCELLS, 256>>>(ln_w, ln_b);
    mlp1_kernel<<<NCELLS * 4, 256, M2_SMEM>>>(b1);
    mlp2_kernel<<<NCELLS, 256, M2_SMEM>>>(b2, gamma, out);
}